// round 9
// baseline (speedup 1.0000x reference)
#include <cuda_runtime.h>

#define BLOCK 128
#define RPT 6      // rows per thread
#define NPAIR 3    // f32x2 row-pairs per thread
#define BETA_C 0.99f
#define EPS_V 1e-3f
#define LOG_2PI_C 1.8378770664093453f

__device__ double g_accum = 0.0;
__device__ unsigned int g_count = 0;

static __device__ __forceinline__ unsigned long long pack2(float lo, float hi) {
    unsigned long long r;
    asm("mov.b64 %0, {%1, %2};" : "=l"(r) : "f"(lo), "f"(hi));
    return r;
}
static __device__ __forceinline__ void unpack2(unsigned long long v, float& lo, float& hi) {
    asm("mov.b64 {%0, %1}, %2;" : "=f"(lo), "=f"(hi) : "l"(v));
}
static __device__ __forceinline__ unsigned long long ffma2(unsigned long long a,
                                                           unsigned long long b,
                                                           unsigned long long c) {
    unsigned long long d;
    asm("fma.rn.f32x2 %0, %1, %2, %3;" : "=l"(d) : "l"(a), "l"(b), "l"(c));
    return d;
}
static __device__ __forceinline__ unsigned long long relu2(unsigned long long a) {
    float lo, hi;
    unpack2(a, lo, hi);
    lo = fmaxf(lo, 0.0f);
    hi = fmaxf(hi, 0.0f);
    return pack2(lo, hi);
}

static __device__ __forceinline__ unsigned smem_u32(const void* p) {
    return (unsigned)__cvta_generic_to_shared(p);
}

// Per-row epilogue: Lyapunov scaling + rsample + NLL contribution.
static __device__ __forceinline__ float row_epilogue(
    float x0, float x1, float mu0, float mu1, float lv0, float lv1,
    float y0, float y1, float e0, float e1,
    float wv00, float wv01, float wv10, float wv11,
    float& fx0, float& fx1)
{
    float t0 = fmaf(x1, wv10, x0 * wv00);
    float t1 = fmaf(x1, wv11, x0 * wv01);
    float Vx = fmaf(t0, t0, fmaf(t1, t1, EPS_V));
    float m0 = fmaf(mu1, wv10, mu0 * wv00);
    float m1 = fmaf(mu1, wv11, mu0 * wv01);
    float Vmu = fmaf(m0, m0, fmaf(m1, m1, EPS_V));
    // a - relu(a-b) == min(a,b)
    float scale = __fdividef(fminf(BETA_C * Vx, Vmu), Vmu);
    float ms0 = mu0 * scale, ms1 = mu1 * scale;
    // sqrt(var) = exp(0.5*lv); 1/var = exp(-lv); log(var) = lv
    float s0 = __expf(0.5f * lv0), s1 = __expf(0.5f * lv1);
    fx0 = fmaf(s0, e0, ms0);
    fx1 = fmaf(s1, e1, ms1);
    float iv0 = __expf(-lv0), iv1 = __expf(-lv1);
    float d0 = y0 - ms0, d1 = y1 - ms1;
    return 0.5f * (fmaf(d0 * d0, iv0, d1 * d1 * iv1) + lv0 + lv1 + 2.0f * LOG_2PI_C);
}

__global__ void __launch_bounds__(BLOCK, 8) mdn_main(
    const float* __restrict__ x, const float* __restrict__ y, const float* __restrict__ eps,
    const float* __restrict__ W1, const float* __restrict__ b1,
    const float* __restrict__ W2, const float* __restrict__ b2,
    const float* __restrict__ Wv, float* __restrict__ out_fx,
    int B, long out_last)
{
    // Scalar weights, 32 bytes per hidden unit (two LDS.128 per j):
    // sW[j][0] = {W1[0][j], W1[1][j], b1[j], W2[j][0]}
    // sW[j][1] = {W2[j][1], W2[j][2], W2[j][3], pad}
    __shared__ float4 sW[64][2];
    // cp.async staging for y / eps (consumed in the epilogue).
    __shared__ float4 sY[BLOCK][NPAIR];
    __shared__ float4 sE[BLOCK][NPAIR];

    int tid = threadIdx.x;
    if (tid < 64) {
        float4 w2v = ((const float4*)W2)[tid];
        sW[tid][0] = make_float4(W1[tid], W1[64 + tid], b1[tid], w2v.x);
        sW[tid][1] = make_float4(w2v.y, w2v.z, w2v.w, 0.0f);
    }
    __syncthreads();

    int t = blockIdx.x * BLOCK + tid;
    int row0 = t * RPT;
    float nll = 0.0f;

    if (row0 + RPT <= B) {
        const float4* X4 = (const float4*)x + (size_t)t * NPAIR;
        const float4* Y4 = (const float4*)y + (size_t)t * NPAIR;
        const float4* E4 = (const float4*)eps + (size_t)t * NPAIR;
        float4* O4 = (float4*)out_fx + (size_t)t * NPAIR;

        // Kick off async copies of y/eps; the j-loop hides their latency.
        #pragma unroll
        for (int p = 0; p < NPAIR; p++) {
            asm volatile("cp.async.cg.shared.global [%0], [%1], 16;"
                         :: "r"(smem_u32(&sY[tid][p])), "l"(Y4 + p) : "memory");
            asm volatile("cp.async.cg.shared.global [%0], [%1], 16;"
                         :: "r"(smem_u32(&sE[tid][p])), "l"(E4 + p) : "memory");
        }
        asm volatile("cp.async.commit_group;" ::: "memory");

        unsigned long long x0p[NPAIR], x1p[NPAIR];
        unsigned long long a0[NPAIR], a1[NPAIR], a2[NPAIR], a3[NPAIR];

        #pragma unroll
        for (int p = 0; p < NPAIR; p++) {
            float4 xv = X4[p];                 // rows 2p, 2p+1: (x0A, x1A, x0B, x1B)
            x0p[p] = pack2(xv.x, xv.z);
            x1p[p] = pack2(xv.y, xv.w);
            a0[p] = 0ULL; a1[p] = 0ULL; a2[p] = 0ULL; a3[p] = 0ULL;
        }

        #pragma unroll 2
        for (int j = 0; j < 64; j++) {
            float4 u = sW[j][0];
            float4 v = sW[j][1];
            unsigned long long A0 = pack2(u.x, u.x);
            unsigned long long A1 = pack2(u.y, u.y);
            unsigned long long Bb = pack2(u.z, u.z);
            unsigned long long W0 = pack2(u.w, u.w);
            unsigned long long Wc1 = pack2(v.x, v.x);
            unsigned long long Wc2 = pack2(v.y, v.y);
            unsigned long long Wc3 = pack2(v.z, v.z);
            #pragma unroll
            for (int p = 0; p < NPAIR; p++) {
                unsigned long long h = ffma2(x0p[p], A0, ffma2(x1p[p], A1, Bb));
                h = relu2(h);
                a0[p] = ffma2(h, W0,  a0[p]);
                a1[p] = ffma2(h, Wc1, a1[p]);
                a2[p] = ffma2(h, Wc2, a2[p]);
                a3[p] = ffma2(h, Wc3, a3[p]);
            }
        }

        // Scalars loaded after the mainloop to keep its live set small.
        float wv00 = __ldg(Wv + 0), wv01 = __ldg(Wv + 1);
        float wv10 = __ldg(Wv + 2), wv11 = __ldg(Wv + 3);
        float c0 = __ldg(b2 + 0), c1 = __ldg(b2 + 1), c2 = __ldg(b2 + 2), c3 = __ldg(b2 + 3);

        // y/eps have long since landed in smem.
        asm volatile("cp.async.wait_group 0;" ::: "memory");

        #pragma unroll
        for (int p = 0; p < NPAIR; p++) {
            float mu0A, mu0B, mu1A, mu1B, lv0A, lv0B, lv1A, lv1B;
            float x0A, x0B, x1A, x1B;
            unpack2(a0[p], mu0A, mu0B);
            unpack2(a1[p], mu1A, mu1B);
            unpack2(a2[p], lv0A, lv0B);
            unpack2(a3[p], lv1A, lv1B);
            unpack2(x0p[p], x0A, x0B);
            unpack2(x1p[p], x1A, x1B);
            mu0A += c0; mu0B += c0; mu1A += c1; mu1B += c1;
            lv0A += c2; lv0B += c2; lv1A += c3; lv1B += c3;
            float4 yv = sY[tid][p];
            float4 ev = sE[tid][p];
            float fx0A, fx1A, fx0B, fx1B;
            nll += row_epilogue(x0A, x1A, mu0A, mu1A, lv0A, lv1A,
                                yv.x, yv.y, ev.x, ev.y,
                                wv00, wv01, wv10, wv11, fx0A, fx1A);
            nll += row_epilogue(x0B, x1B, mu0B, mu1B, lv0B, lv1B,
                                yv.z, yv.w, ev.z, ev.w,
                                wv00, wv01, wv10, wv11, fx0B, fx1B);
            O4[p] = make_float4(fx0A, fx1A, fx0B, fx1B);
        }
    } else if (row0 < B) {
        // Tail fallback.
        float wv00 = __ldg(Wv + 0), wv01 = __ldg(Wv + 1);
        float wv10 = __ldg(Wv + 2), wv11 = __ldg(Wv + 3);
        float c0 = __ldg(b2 + 0), c1 = __ldg(b2 + 1), c2 = __ldg(b2 + 2), c3 = __ldg(b2 + 3);
        for (int r = row0; r < B; r++) {
            float x0 = x[2 * (size_t)r], x1 = x[2 * (size_t)r + 1];
            float f0 = c0, f1 = c1, f2 = c2, f3 = c3;
            for (int j = 0; j < 64; j++) {
                float4 u = sW[j][0];
                float4 v = sW[j][1];
                float h = fmaxf(fmaf(x0, u.x, fmaf(x1, u.y, u.z)), 0.0f);
                f0 = fmaf(h, u.w, f0);
                f1 = fmaf(h, v.x, f1);
                f2 = fmaf(h, v.y, f2);
                f3 = fmaf(h, v.z, f3);
            }
            float fx0, fx1;
            nll += row_epilogue(x0, x1, f0, f1, f2, f3,
                                y[2 * (size_t)r], y[2 * (size_t)r + 1],
                                eps[2 * (size_t)r], eps[2 * (size_t)r + 1],
                                wv00, wv01, wv10, wv11, fx0, fx1);
            out_fx[2 * (size_t)r] = fx0;
            out_fx[2 * (size_t)r + 1] = fx1;
        }
    }

    // Block reduction of nll (float) -> one double atomic per block.
    unsigned mask = 0xFFFFFFFFu;
    #pragma unroll
    for (int off = 16; off > 0; off >>= 1)
        nll += __shfl_down_sync(mask, nll, off);
    __shared__ float red[BLOCK / 32];
    __shared__ bool s_is_last;
    int wid = tid >> 5, lid = tid & 31;
    if (lid == 0) red[wid] = nll;
    __syncthreads();
    if (wid == 0) {
        float v = (lid < BLOCK / 32) ? red[lid] : 0.0f;
        #pragma unroll
        for (int off = 2; off > 0; off >>= 1)
            v += __shfl_down_sync(mask, v, off);
        if (lid == 0) {
            atomicAdd(&g_accum, (double)v);
            __threadfence();
            unsigned int done = atomicAdd(&g_count, 1u);
            s_is_last = (done == gridDim.x - 1);
        }
    }
    __syncthreads();
    // Last block to finish: publish the scalar and reset globals for next replay.
    if (s_is_last && tid == 0) {
        double total = *((volatile double*)&g_accum);
        out_fx[out_last] = (float)total;
        *((volatile double*)&g_accum) = 0.0;
        __threadfence();
        *((volatile unsigned int*)&g_count) = 0u;
    }
}

extern "C" void kernel_launch(void* const* d_in, const int* in_sizes, int n_in,
                              void* d_out, int out_size) {
    const float* x   = (const float*)d_in[0];
    const float* y   = (const float*)d_in[1];
    const float* eps = (const float*)d_in[2];
    const float* W1  = (const float*)d_in[3];
    const float* b1  = (const float*)d_in[4];
    const float* W2  = (const float*)d_in[5];
    const float* b2  = (const float*)d_in[6];
    const float* Wv  = (const float*)d_in[7];
    float* out = (float*)d_out;

    int B = in_sizes[0] / 2;
    long nthreads = ((long)B + RPT - 1) / RPT;
    int blocks = (int)((nthreads + BLOCK - 1) / BLOCK);

    mdn_main<<<blocks, BLOCK>>>(x, y, eps, W1, b1, W2, b2, Wv, out,
                                B, (long)out_size - 1);
}

// round 10
// speedup vs baseline: 1.0912x; 1.0912x over previous
#include <cuda_runtime.h>

#define BLOCK 128
#define RPT 6      // rows per thread
#define NPAIR 3    // f32x2 row-pairs per thread
#define BETA_C 0.99f
#define EPS_V 1e-3f
#define LOG_2PI_C 1.8378770664093453f

__device__ double g_accum = 0.0;
__device__ unsigned int g_count = 0;

static __device__ __forceinline__ unsigned long long pack2(float lo, float hi) {
    unsigned long long r;
    asm("mov.b64 %0, {%1, %2};" : "=l"(r) : "f"(lo), "f"(hi));
    return r;
}
static __device__ __forceinline__ void unpack2(unsigned long long v, float& lo, float& hi) {
    asm("mov.b64 {%0, %1}, %2;" : "=f"(lo), "=f"(hi) : "l"(v));
}
static __device__ __forceinline__ unsigned long long ffma2(unsigned long long a,
                                                           unsigned long long b,
                                                           unsigned long long c) {
    unsigned long long d;
    asm("fma.rn.f32x2 %0, %1, %2, %3;" : "=l"(d) : "l"(a), "l"(b), "l"(c));
    return d;
}
static __device__ __forceinline__ unsigned long long relu2(unsigned long long a) {
    float lo, hi;
    unpack2(a, lo, hi);
    lo = fmaxf(lo, 0.0f);
    hi = fmaxf(hi, 0.0f);
    return pack2(lo, hi);
}

// Per-row epilogue: Lyapunov scaling + rsample + NLL contribution.
static __device__ __forceinline__ float row_epilogue(
    float x0, float x1, float mu0, float mu1, float lv0, float lv1,
    float y0, float y1, float e0, float e1,
    float wv00, float wv01, float wv10, float wv11,
    float& fx0, float& fx1)
{
    float t0 = fmaf(x1, wv10, x0 * wv00);
    float t1 = fmaf(x1, wv11, x0 * wv01);
    float Vx = fmaf(t0, t0, fmaf(t1, t1, EPS_V));
    float m0 = fmaf(mu1, wv10, mu0 * wv00);
    float m1 = fmaf(mu1, wv11, mu0 * wv01);
    float Vmu = fmaf(m0, m0, fmaf(m1, m1, EPS_V));
    // a - relu(a-b) == min(a,b)
    float scale = __fdividef(fminf(BETA_C * Vx, Vmu), Vmu);
    float ms0 = mu0 * scale, ms1 = mu1 * scale;
    // sqrt(var) = exp(0.5*lv); 1/var = exp(-lv); log(var) = lv
    float s0 = __expf(0.5f * lv0), s1 = __expf(0.5f * lv1);
    fx0 = fmaf(s0, e0, ms0);
    fx1 = fmaf(s1, e1, ms1);
    float iv0 = __expf(-lv0), iv1 = __expf(-lv1);
    float d0 = y0 - ms0, d1 = y1 - ms1;
    return 0.5f * (fmaf(d0 * d0, iv0, d1 * d1 * iv1) + lv0 + lv1 + 2.0f * LOG_2PI_C);
}

__global__ void __launch_bounds__(BLOCK) mdn_main(
    const float* __restrict__ x, const float* __restrict__ y, const float* __restrict__ eps,
    const float* __restrict__ W1, const float* __restrict__ b1,
    const float* __restrict__ W2, const float* __restrict__ b2,
    const float* __restrict__ Wv, float* __restrict__ out_fx,
    int B, long out_last)
{
    // Scalar weights, 32 bytes per hidden unit (two LDS.128 per j):
    // sW[j][0] = {W1[0][j], W1[1][j], b1[j], W2[j][0]}
    // sW[j][1] = {W2[j][1], W2[j][2], W2[j][3], pad}
    __shared__ float4 sW[64][2];

    int tid = threadIdx.x;
    if (tid < 64) {
        float4 w2v = ((const float4*)W2)[tid];
        sW[tid][0] = make_float4(W1[tid], W1[64 + tid], b1[tid], w2v.x);
        sW[tid][1] = make_float4(w2v.y, w2v.z, w2v.w, 0.0f);
    }
    __syncthreads();

    int t = blockIdx.x * BLOCK + tid;
    int row0 = t * RPT;
    float nll = 0.0f;

    if (row0 + RPT <= B) {
        const float4* X4 = (const float4*)x + (size_t)t * NPAIR;
        const float4* Y4 = (const float4*)y + (size_t)t * NPAIR;
        const float4* E4 = (const float4*)eps + (size_t)t * NPAIR;
        float4* O4 = (float4*)out_fx + (size_t)t * NPAIR;

        unsigned long long x0p[NPAIR], x1p[NPAIR];
        unsigned long long a0[NPAIR], a1[NPAIR], a2[NPAIR], a3[NPAIR];

        #pragma unroll
        for (int p = 0; p < NPAIR; p++) {
            float4 xv = X4[p];                 // rows 2p, 2p+1: (x0A, x1A, x0B, x1B)
            x0p[p] = pack2(xv.x, xv.z);
            x1p[p] = pack2(xv.y, xv.w);
            a0[p] = 0ULL; a1[p] = 0ULL; a2[p] = 0ULL; a3[p] = 0ULL;
        }

        #pragma unroll 4
        for (int j = 0; j < 64; j++) {
            float4 u = sW[j][0];
            float4 v = sW[j][1];
            unsigned long long A0 = pack2(u.x, u.x);
            unsigned long long A1 = pack2(u.y, u.y);
            unsigned long long Bb = pack2(u.z, u.z);
            unsigned long long W0 = pack2(u.w, u.w);
            unsigned long long Wc1 = pack2(v.x, v.x);
            unsigned long long Wc2 = pack2(v.y, v.y);
            unsigned long long Wc3 = pack2(v.z, v.z);
            #pragma unroll
            for (int p = 0; p < NPAIR; p++) {
                unsigned long long h = ffma2(x0p[p], A0, ffma2(x1p[p], A1, Bb));
                h = relu2(h);
                a0[p] = ffma2(h, W0,  a0[p]);
                a1[p] = ffma2(h, Wc1, a1[p]);
                a2[p] = ffma2(h, Wc2, a2[p]);
                a3[p] = ffma2(h, Wc3, a3[p]);
            }
        }

        // Scalars loaded after the mainloop to keep its live set small.
        float wv00 = __ldg(Wv + 0), wv01 = __ldg(Wv + 1);
        float wv10 = __ldg(Wv + 2), wv11 = __ldg(Wv + 3);
        float c0 = __ldg(b2 + 0), c1 = __ldg(b2 + 1), c2 = __ldg(b2 + 2), c3 = __ldg(b2 + 3);

        #pragma unroll
        for (int p = 0; p < NPAIR; p++) {
            float mu0A, mu0B, mu1A, mu1B, lv0A, lv0B, lv1A, lv1B;
            float x0A, x0B, x1A, x1B;
            unpack2(a0[p], mu0A, mu0B);
            unpack2(a1[p], mu1A, mu1B);
            unpack2(a2[p], lv0A, lv0B);
            unpack2(a3[p], lv1A, lv1B);
            unpack2(x0p[p], x0A, x0B);
            unpack2(x1p[p], x1A, x1B);
            mu0A += c0; mu0B += c0; mu1A += c1; mu1B += c1;
            lv0A += c2; lv0B += c2; lv1A += c3; lv1B += c3;
            float4 yv = Y4[p];
            float4 ev = E4[p];
            float fx0A, fx1A, fx0B, fx1B;
            nll += row_epilogue(x0A, x1A, mu0A, mu1A, lv0A, lv1A,
                                yv.x, yv.y, ev.x, ev.y,
                                wv00, wv01, wv10, wv11, fx0A, fx1A);
            nll += row_epilogue(x0B, x1B, mu0B, mu1B, lv0B, lv1B,
                                yv.z, yv.w, ev.z, ev.w,
                                wv00, wv01, wv10, wv11, fx0B, fx1B);
            O4[p] = make_float4(fx0A, fx1A, fx0B, fx1B);
        }
    } else if (row0 < B) {
        // Tail fallback.
        float wv00 = __ldg(Wv + 0), wv01 = __ldg(Wv + 1);
        float wv10 = __ldg(Wv + 2), wv11 = __ldg(Wv + 3);
        float c0 = __ldg(b2 + 0), c1 = __ldg(b2 + 1), c2 = __ldg(b2 + 2), c3 = __ldg(b2 + 3);
        for (int r = row0; r < B; r++) {
            float x0 = x[2 * (size_t)r], x1 = x[2 * (size_t)r + 1];
            float f0 = c0, f1 = c1, f2 = c2, f3 = c3;
            for (int j = 0; j < 64; j++) {
                float4 u = sW[j][0];
                float4 v = sW[j][1];
                float h = fmaxf(fmaf(x0, u.x, fmaf(x1, u.y, u.z)), 0.0f);
                f0 = fmaf(h, u.w, f0);
                f1 = fmaf(h, v.x, f1);
                f2 = fmaf(h, v.y, f2);
                f3 = fmaf(h, v.z, f3);
            }
            float fx0, fx1;
            nll += row_epilogue(x0, x1, f0, f1, f2, f3,
                                y[2 * (size_t)r], y[2 * (size_t)r + 1],
                                eps[2 * (size_t)r], eps[2 * (size_t)r + 1],
                                wv00, wv01, wv10, wv11, fx0, fx1);
            out_fx[2 * (size_t)r] = fx0;
            out_fx[2 * (size_t)r + 1] = fx1;
        }
    }

    // Block reduction of nll (float) -> one double atomic per block.
    unsigned mask = 0xFFFFFFFFu;
    #pragma unroll
    for (int off = 16; off > 0; off >>= 1)
        nll += __shfl_down_sync(mask, nll, off);
    __shared__ float red[BLOCK / 32];
    __shared__ bool s_is_last;
    int wid = tid >> 5, lid = tid & 31;
    if (lid == 0) red[wid] = nll;
    __syncthreads();
    if (wid == 0) {
        float v = (lid < BLOCK / 32) ? red[lid] : 0.0f;
        #pragma unroll
        for (int off = 2; off > 0; off >>= 1)
            v += __shfl_down_sync(mask, v, off);
        if (lid == 0) {
            atomicAdd(&g_accum, (double)v);
            __threadfence();
            unsigned int done = atomicAdd(&g_count, 1u);
            s_is_last = (done == gridDim.x - 1);
        }
    }
    __syncthreads();
    // Last block to finish: publish the scalar and reset globals for next replay.
    if (s_is_last && tid == 0) {
        double total = *((volatile double*)&g_accum);
        out_fx[out_last] = (float)total;
        *((volatile double*)&g_accum) = 0.0;
        __threadfence();
        *((volatile unsigned int*)&g_count) = 0u;
    }
}

extern "C" void kernel_launch(void* const* d_in, const int* in_sizes, int n_in,
                              void* d_out, int out_size) {
    const float* x   = (const float*)d_in[0];
    const float* y   = (const float*)d_in[1];
    const float* eps = (const float*)d_in[2];
    const float* W1  = (const float*)d_in[3];
    const float* b1  = (const float*)d_in[4];
    const float* W2  = (const float*)d_in[5];
    const float* b2  = (const float*)d_in[6];
    const float* Wv  = (const float*)d_in[7];
    float* out = (float*)d_out;

    int B = in_sizes[0] / 2;
    long nthreads = ((long)B + RPT - 1) / RPT;
    int blocks = (int)((nthreads + BLOCK - 1) / BLOCK);

    mdn_main<<<blocks, BLOCK>>>(x, y, eps, W1, b1, W2, b2, Wv, out,
                                B, (long)out_size - 1);
}

// round 11
// speedup vs baseline: 1.0983x; 1.0065x over previous
#include <cuda_runtime.h>

#define BLOCK 128
#define RPT 6      // rows per thread
#define NPAIR 3    // f32x2 row-pairs per thread
#define BETA_C 0.99f
#define EPS_V 1e-3f
#define LOG_2PI_C 1.8378770664093453f

__device__ double g_accum = 0.0;
__device__ unsigned int g_count = 0;

static __device__ __forceinline__ unsigned long long pack2(float lo, float hi) {
    unsigned long long r;
    asm("mov.b64 %0, {%1, %2};" : "=l"(r) : "f"(lo), "f"(hi));
    return r;
}
static __device__ __forceinline__ void unpack2(unsigned long long v, float& lo, float& hi) {
    asm("mov.b64 {%0, %1}, %2;" : "=f"(lo), "=f"(hi) : "l"(v));
}
static __device__ __forceinline__ unsigned long long ffma2(unsigned long long a,
                                                           unsigned long long b,
                                                           unsigned long long c) {
    unsigned long long d;
    asm("fma.rn.f32x2 %0, %1, %2, %3;" : "=l"(d) : "l"(a), "l"(b), "l"(c));
    return d;
}
static __device__ __forceinline__ unsigned long long relu2(unsigned long long a) {
    float lo, hi;
    unpack2(a, lo, hi);
    lo = fmaxf(lo, 0.0f);
    hi = fmaxf(hi, 0.0f);
    return pack2(lo, hi);
}

// Per-row epilogue: Lyapunov scaling + rsample + NLL contribution.
static __device__ __forceinline__ float row_epilogue(
    float x0, float x1, float mu0, float mu1, float lv0, float lv1,
    float y0, float y1, float e0, float e1,
    float wv00, float wv01, float wv10, float wv11,
    float& fx0, float& fx1)
{
    float t0 = fmaf(x1, wv10, x0 * wv00);
    float t1 = fmaf(x1, wv11, x0 * wv01);
    float Vx = fmaf(t0, t0, fmaf(t1, t1, EPS_V));
    float m0 = fmaf(mu1, wv10, mu0 * wv00);
    float m1 = fmaf(mu1, wv11, mu0 * wv01);
    float Vmu = fmaf(m0, m0, fmaf(m1, m1, EPS_V));
    // a - relu(a-b) == min(a,b)
    float scale = __fdividef(fminf(BETA_C * Vx, Vmu), Vmu);
    float ms0 = mu0 * scale, ms1 = mu1 * scale;
    // sqrt(var) = exp(0.5*lv); 1/var = exp(-lv); log(var) = lv
    float s0 = __expf(0.5f * lv0), s1 = __expf(0.5f * lv1);
    fx0 = fmaf(s0, e0, ms0);
    fx1 = fmaf(s1, e1, ms1);
    float iv0 = __expf(-lv0), iv1 = __expf(-lv1);
    float d0 = y0 - ms0, d1 = y1 - ms1;
    return 0.5f * (fmaf(d0 * d0, iv0, d1 * d1 * iv1) + lv0 + lv1 + 2.0f * LOG_2PI_C);
}

__global__ void __launch_bounds__(BLOCK) mdn_main(
    const float* __restrict__ x, const float* __restrict__ y, const float* __restrict__ eps,
    const float* __restrict__ W1, const float* __restrict__ b1,
    const float* __restrict__ W2, const float* __restrict__ b2,
    const float* __restrict__ Wv, float* __restrict__ out_fx,
    int B, long out_last)
{
    // Scalar weights, 32 bytes per hidden unit (two LDS.128 per j):
    // sW[j][0] = {W1[0][j], W1[1][j], b1[j], W2[j][0]}
    // sW[j][1] = {W2[j][1], W2[j][2], W2[j][3], pad}
    __shared__ float4 sW[64][2];

    int tid = threadIdx.x;
    if (tid < 64) {
        float4 w2v = ((const float4*)W2)[tid];
        sW[tid][0] = make_float4(W1[tid], W1[64 + tid], b1[tid], w2v.x);
        sW[tid][1] = make_float4(w2v.y, w2v.z, w2v.w, 0.0f);
    }
    __syncthreads();

    int t = blockIdx.x * BLOCK + tid;
    int row0 = t * RPT;
    float nll = 0.0f;

    if (row0 + RPT <= B) {
        const float4* X4 = (const float4*)x + (size_t)t * NPAIR;
        const float4* Y4 = (const float4*)y + (size_t)t * NPAIR;
        const float4* E4 = (const float4*)eps + (size_t)t * NPAIR;
        float4* O4 = (float4*)out_fx + (size_t)t * NPAIR;

        unsigned long long x0p[NPAIR], x1p[NPAIR];
        unsigned long long a0[NPAIR], a1[NPAIR], a2[NPAIR], a3[NPAIR];

        #pragma unroll
        for (int p = 0; p < NPAIR; p++) {
            float4 xv = X4[p];                 // rows 2p, 2p+1: (x0A, x1A, x0B, x1B)
            x0p[p] = pack2(xv.x, xv.z);
            x1p[p] = pack2(xv.y, xv.w);
            a0[p] = 0ULL; a1[p] = 0ULL; a2[p] = 0ULL; a3[p] = 0ULL;
        }

        #pragma unroll 8
        for (int j = 0; j < 64; j++) {
            float4 u = sW[j][0];
            float4 v = sW[j][1];
            unsigned long long A0 = pack2(u.x, u.x);
            unsigned long long A1 = pack2(u.y, u.y);
            unsigned long long Bb = pack2(u.z, u.z);
            unsigned long long W0 = pack2(u.w, u.w);
            unsigned long long Wc1 = pack2(v.x, v.x);
            unsigned long long Wc2 = pack2(v.y, v.y);
            unsigned long long Wc3 = pack2(v.z, v.z);
            #pragma unroll
            for (int p = 0; p < NPAIR; p++) {
                unsigned long long h = ffma2(x0p[p], A0, ffma2(x1p[p], A1, Bb));
                h = relu2(h);
                a0[p] = ffma2(h, W0,  a0[p]);
                a1[p] = ffma2(h, Wc1, a1[p]);
                a2[p] = ffma2(h, Wc2, a2[p]);
                a3[p] = ffma2(h, Wc3, a3[p]);
            }
        }

        // Scalars loaded after the mainloop to keep its live set small.
        float wv00 = __ldg(Wv + 0), wv01 = __ldg(Wv + 1);
        float wv10 = __ldg(Wv + 2), wv11 = __ldg(Wv + 3);
        float c0 = __ldg(b2 + 0), c1 = __ldg(b2 + 1), c2 = __ldg(b2 + 2), c3 = __ldg(b2 + 3);

        #pragma unroll
        for (int p = 0; p < NPAIR; p++) {
            float mu0A, mu0B, mu1A, mu1B, lv0A, lv0B, lv1A, lv1B;
            float x0A, x0B, x1A, x1B;
            unpack2(a0[p], mu0A, mu0B);
            unpack2(a1[p], mu1A, mu1B);
            unpack2(a2[p], lv0A, lv0B);
            unpack2(a3[p], lv1A, lv1B);
            unpack2(x0p[p], x0A, x0B);
            unpack2(x1p[p], x1A, x1B);
            mu0A += c0; mu0B += c0; mu1A += c1; mu1B += c1;
            lv0A += c2; lv0B += c2; lv1A += c3; lv1B += c3;
            float4 yv = Y4[p];
            float4 ev = E4[p];
            float fx0A, fx1A, fx0B, fx1B;
            nll += row_epilogue(x0A, x1A, mu0A, mu1A, lv0A, lv1A,
                                yv.x, yv.y, ev.x, ev.y,
                                wv00, wv01, wv10, wv11, fx0A, fx1A);
            nll += row_epilogue(x0B, x1B, mu0B, mu1B, lv0B, lv1B,
                                yv.z, yv.w, ev.z, ev.w,
                                wv00, wv01, wv10, wv11, fx0B, fx1B);
            O4[p] = make_float4(fx0A, fx1A, fx0B, fx1B);
        }
    } else if (row0 < B) {
        // Tail fallback.
        float wv00 = __ldg(Wv + 0), wv01 = __ldg(Wv + 1);
        float wv10 = __ldg(Wv + 2), wv11 = __ldg(Wv + 3);
        float c0 = __ldg(b2 + 0), c1 = __ldg(b2 + 1), c2 = __ldg(b2 + 2), c3 = __ldg(b2 + 3);
        for (int r = row0; r < B; r++) {
            float x0 = x[2 * (size_t)r], x1 = x[2 * (size_t)r + 1];
            float f0 = c0, f1 = c1, f2 = c2, f3 = c3;
            for (int j = 0; j < 64; j++) {
                float4 u = sW[j][0];
                float4 v = sW[j][1];
                float h = fmaxf(fmaf(x0, u.x, fmaf(x1, u.y, u.z)), 0.0f);
                f0 = fmaf(h, u.w, f0);
                f1 = fmaf(h, v.x, f1);
                f2 = fmaf(h, v.y, f2);
                f3 = fmaf(h, v.z, f3);
            }
            float fx0, fx1;
            nll += row_epilogue(x0, x1, f0, f1, f2, f3,
                                y[2 * (size_t)r], y[2 * (size_t)r + 1],
                                eps[2 * (size_t)r], eps[2 * (size_t)r + 1],
                                wv00, wv01, wv10, wv11, fx0, fx1);
            out_fx[2 * (size_t)r] = fx0;
            out_fx[2 * (size_t)r + 1] = fx1;
        }
    }

    // Block reduction of nll (float) -> one double atomic per block.
    unsigned mask = 0xFFFFFFFFu;
    #pragma unroll
    for (int off = 16; off > 0; off >>= 1)
        nll += __shfl_down_sync(mask, nll, off);
    __shared__ float red[BLOCK / 32];
    __shared__ bool s_is_last;
    int wid = tid >> 5, lid = tid & 31;
    if (lid == 0) red[wid] = nll;
    __syncthreads();
    if (wid == 0) {
        float v = (lid < BLOCK / 32) ? red[lid] : 0.0f;
        #pragma unroll
        for (int off = 2; off > 0; off >>= 1)
            v += __shfl_down_sync(mask, v, off);
        if (lid == 0) {
            atomicAdd(&g_accum, (double)v);
            __threadfence();
            unsigned int done = atomicAdd(&g_count, 1u);
            s_is_last = (done == gridDim.x - 1);
        }
    }
    __syncthreads();
    // Last block to finish: publish the scalar and reset globals for next replay.
    if (s_is_last && tid == 0) {
        double total = *((volatile double*)&g_accum);
        out_fx[out_last] = (float)total;
        *((volatile double*)&g_accum) = 0.0;
        __threadfence();
        *((volatile unsigned int*)&g_count) = 0u;
    }
}

extern "C" void kernel_launch(void* const* d_in, const int* in_sizes, int n_in,
                              void* d_out, int out_size) {
    const float* x   = (const float*)d_in[0];
    const float* y   = (const float*)d_in[1];
    const float* eps = (const float*)d_in[2];
    const float* W1  = (const float*)d_in[3];
    const float* b1  = (const float*)d_in[4];
    const float* W2  = (const float*)d_in[5];
    const float* b2  = (const float*)d_in[6];
    const float* Wv  = (const float*)d_in[7];
    float* out = (float*)d_out;

    int B = in_sizes[0] / 2;
    long nthreads = ((long)B + RPT - 1) / RPT;
    int blocks = (int)((nthreads + BLOCK - 1) / BLOCK);

    mdn_main<<<blocks, BLOCK>>>(x, y, eps, W1, b1, W2, b2, Wv, out,
                                B, (long)out_size - 1);
}